// round 7
// baseline (speedup 1.0000x reference)
#include <cuda_runtime.h>
#include <math.h>

#define BB   8
#define NN   2048
#define KNN  20
#define CLSN 40
#define EPSBN 1e-5f

// ---------------- scratch (static __device__ — no allocations) ----------------
__device__ float g_xx[BB * NN];
__device__ int   g_idx[BB * NN * KNN];
__device__ float g_feat[2][BB * 64 * NN];            // ping-pong feature maps
__device__ float g_hacc[(size_t)BB * NN * KNN * 64]; // accumulated w5 @ [y1..y4]
__device__ float g_hm[BB * 64 * NN];                 // after bn5+lrelu+max_k
__device__ float g_h2t[BB * NN * 256];               // conv6 out, [b][n][256]
__device__ float g_gvec[BB * 512];                   // [max | mean]

// ---------------- squared norms ----------------
template <int C>
__global__ void xx_kernel(const float* __restrict__ extx, int sel) {
    const float* xin = (sel < 0) ? extx : g_feat[sel];
    int t = blockIdx.x * blockDim.x + threadIdx.x;
    if (t >= BB * NN) return;
    int b = t / NN, n = t % NN;
    float s = 0.f;
#pragma unroll
    for (int c = 0; c < C; c++) {
        float v = xin[(b * C + c) * NN + n];
        s += v * v;
    }
    g_xx[t] = s;
}

// ---------------- top-k maintenance (streaming insertion, stable) ----------------
struct TopK {
    float v[KNN];
    int   id[KNN];
    float thr;
    __device__ __forceinline__ void init() {
#pragma unroll
        for (int i = 0; i < KNN; i++) { v[i] = -3e38f; id[i] = 0; }
        thr = -3e38f;
    }
    __device__ __forceinline__ void push(float val, int m) {
        if (val > thr) {
            int p = KNN - 1;
            while (p > 0 && v[p - 1] < val) {
                v[p] = v[p - 1];
                id[p] = id[p - 1];
                p--;
            }
            v[p] = val;
            id[p] = m;
            thr = v[KNN - 1];
        }
    }
};

// ---------------- kNN, C=3 (stage 1) ----------------
__global__ __launch_bounds__(128) void knn3_kernel(const float* __restrict__ x) {
    __shared__ float s0[NN], s1[NN], s2[NN], sxx[NN]; // 32KB
    int b = blockIdx.y;
    int n = blockIdx.x * 128 + threadIdx.x;
    for (int i = threadIdx.x; i < NN; i += 128) {
        s0[i] = x[(b * 3 + 0) * NN + i];
        s1[i] = x[(b * 3 + 1) * NN + i];
        s2[i] = x[(b * 3 + 2) * NN + i];
        sxx[i] = g_xx[b * NN + i];
    }
    __syncthreads();
    float q0 = s0[n], q1 = s1[n], q2 = s2[n], xq = sxx[n];
    TopK tk; tk.init();
    for (int m = 0; m < NN; m++) {
        float d = q0 * s0[m] + q1 * s1[m] + q2 * s2[m];
        tk.push(2.f * d - xq - sxx[m], m);
    }
    int* op = g_idx + (b * NN + n) * KNN;
#pragma unroll
    for (int k = 0; k < KNN; k++) op[k] = tk.id[k];
}

// ---------------- kNN, C=64 (stages 2-4) ----------------
__global__ __launch_bounds__(128) void knn64_kernel(int sel) {
    const float* x = g_feat[sel];
    __shared__ float4 s4[64 * 16]; // [c][j4], 64 candidates per tile
    __shared__ float  sxx[64];
    int b = blockIdx.y;
    int n = blockIdx.x * 128 + threadIdx.x;
    float qf[64];
#pragma unroll
    for (int c = 0; c < 64; c++) qf[c] = x[(b * 64 + c) * NN + n];
    float xq = g_xx[b * NN + n];
    TopK tk; tk.init();
    for (int m0 = 0; m0 < NN; m0 += 64) {
        __syncthreads();
        for (int i = threadIdx.x; i < 64 * 16; i += 128) {
            int c = i >> 4, j = i & 15;
            s4[i] = *(const float4*)&x[(b * 64 + c) * NN + m0 + j * 4];
        }
        if (threadIdx.x < 64) sxx[threadIdx.x] = g_xx[b * NN + m0 + threadIdx.x];
        __syncthreads();
#pragma unroll 4
        for (int j = 0; j < 16; j++) {
            float4 d = make_float4(0.f, 0.f, 0.f, 0.f);
#pragma unroll
            for (int c = 0; c < 64; c++) {
                float4 v = s4[c * 16 + j];
                float  q = qf[c];
                d.x += q * v.x; d.y += q * v.y; d.z += q * v.z; d.w += q * v.w;
            }
            int m = m0 + j * 4;
            tk.push(2.f * d.x - xq - sxx[m - m0 + 0], m + 0);
            tk.push(2.f * d.y - xq - sxx[m - m0 + 1], m + 1);
            tk.push(2.f * d.z - xq - sxx[m - m0 + 2], m + 2);
            tk.push(2.f * d.w - xq - sxx[m - m0 + 3], m + 3);
        }
    }
    int* op = g_idx + (b * NN + n) * KNN;
#pragma unroll
    for (int k = 0; k < KNN; k++) op[k] = tk.id[k];
}

// ---------------- EdgeConv + fused w5-slice accumulate ----------------
// sum[o] = Wd@nbr + (Wc-Wd)@ctr ; y = lrelu0.2(bn(sum)); xout = max_k y
// hacc[p][k][o2] (+)= sum_o w5[o2][w5off+o] * y[k][o]
template <int C>
__global__ __launch_bounds__(96) void edge_kernel(
    const float* __restrict__ extx, int selin,
    const float* __restrict__ w,    // [64][2C]
    const float* __restrict__ bnp,  // [4][64]
    const float* __restrict__ w5,   // [64][256]
    int w5off, int accum, int selout)
{
    __shared__ float sm[C * 64 + 4096 + 3 * 1280];
    __shared__ int   sid[3][KNN];   // per-warp neighbor ids (NO shfl — deadlock-safe)
    const float* xin  = (selin < 0) ? extx : g_feat[selin];
    float*       xout = g_feat[selout];
    float* wd2 = sm;                 // [C][64]: (Wd[j][c], Wd[j+32][c]) interleaved
    float* w52 = sm + C * 64;        // [64][64]: (w5[j][off+o], w5[j+32][off+o])
    int tid = threadIdx.x;
    float* wbuf = sm + C * 64 + 4096 + (tid >> 5) * 1280; // per-warp: nbrs then y

    for (int i = tid; i < C * 64; i += 96) {
        int c = i >> 6, t2 = i & 63, jj = t2 >> 1, hi = t2 & 1;
        wd2[i] = w[(jj + 32 * hi) * (2 * C) + c];
    }
    for (int i = tid; i < 4096; i += 96) {
        int o = i >> 6, t2 = i & 63, jj = t2 >> 1, hi = t2 & 1;
        w52[i] = w5[(jj + 32 * hi) * 256 + w5off + o];
    }
    __syncthreads();

    int lane = tid & 31, warp = tid >> 5;
    int* myid = sid[warp];
    float a0 = bnp[lane] * rsqrtf(bnp[192 + lane] + EPSBN);
    float c0 = bnp[64 + lane] - bnp[128 + lane] * a0;
    float a1 = bnp[32 + lane] * rsqrtf(bnp[224 + lane] + EPSBN);
    float c1 = bnp[96 + lane] - bnp[160 + lane] * a1;

    for (int p = blockIdx.x * 3 + warp; p < BB * NN; p += gridDim.x * 3) {
        int b = p >> 11, n = p & (NN - 1);
        // base = (Wc - Wd) @ ctr
        float base0 = 0.f, base1 = 0.f;
#pragma unroll
        for (int c = 0; c < C; c++) {
            float ctr = __ldg(&xin[(b * C + c) * NN + n]);
            float wc0 = __ldg(&w[lane * (2 * C) + C + c]);
            float wc1 = __ldg(&w[(lane + 32) * (2 * C) + C + c]);
            base0 += (wc0 - wd2[c * 64 + 2 * lane]) * ctr;
            base1 += (wc1 - wd2[c * 64 + 2 * lane + 1]) * ctr;
        }
        if (lane < KNN) myid[lane] = g_idx[p * KNN + lane];
        __syncwarp();
        // gather neighbors into wbuf[c][k]  (indices from shared; divergent
        // trip counts are fine — no warp-collective ops inside)
        for (int t = lane; t < C * KNN; t += 32) {
            int c = t / KNN, k = t - c * KNN;
            wbuf[c * KNN + k] = xin[(b * C + c) * NN + myid[k]];
        }
        __syncwarp();
        // Y = Wd @ nbr + base
        float acc0[KNN], acc1[KNN];
#pragma unroll
        for (int k = 0; k < KNN; k++) { acc0[k] = base0; acc1[k] = base1; }
#pragma unroll 4
        for (int c = 0; c < C; c++) {
            float2 wv = *(const float2*)&wd2[c * 64 + 2 * lane];
            const float4* nb4 = (const float4*)&wbuf[c * KNN];
#pragma unroll
            for (int q = 0; q < 5; q++) {
                float4 v = nb4[q];
                acc0[4 * q + 0] += wv.x * v.x; acc0[4 * q + 1] += wv.x * v.y;
                acc0[4 * q + 2] += wv.x * v.z; acc0[4 * q + 3] += wv.x * v.w;
                acc1[4 * q + 0] += wv.y * v.x; acc1[4 * q + 1] += wv.y * v.y;
                acc1[4 * q + 2] += wv.y * v.z; acc1[4 * q + 3] += wv.y * v.w;
            }
        }
        __syncwarp();
        // bn + lrelu + running max; store y into wbuf[o][k]
        float ym0 = -3e38f, ym1 = -3e38f;
#pragma unroll
        for (int k = 0; k < KNN; k++) {
            float y0 = a0 * acc0[k] + c0; y0 = (y0 >= 0.f) ? y0 : 0.2f * y0;
            float y1 = a1 * acc1[k] + c1; y1 = (y1 >= 0.f) ? y1 : 0.2f * y1;
            ym0 = fmaxf(ym0, y0);
            ym1 = fmaxf(ym1, y1);
            wbuf[lane * KNN + k] = y0;
            wbuf[(lane + 32) * KNN + k] = y1;
        }
        __syncwarp();
        // H = Y @ w5slice^T
        float h0[KNN], h1[KNN];
#pragma unroll
        for (int k = 0; k < KNN; k++) { h0[k] = 0.f; h1[k] = 0.f; }
#pragma unroll 4
        for (int o = 0; o < 64; o++) {
            float2 wv = *(const float2*)&w52[o * 64 + 2 * lane];
            const float4* y4 = (const float4*)&wbuf[o * KNN];
#pragma unroll
            for (int q = 0; q < 5; q++) {
                float4 v = y4[q];
                h0[4 * q + 0] += wv.x * v.x; h0[4 * q + 1] += wv.x * v.y;
                h0[4 * q + 2] += wv.x * v.z; h0[4 * q + 3] += wv.x * v.w;
                h1[4 * q + 0] += wv.y * v.x; h1[4 * q + 1] += wv.y * v.y;
                h1[4 * q + 2] += wv.y * v.z; h1[4 * q + 3] += wv.y * v.w;
            }
        }
        float* hp = g_hacc + (size_t)p * KNN * 64;
        if (accum) {
#pragma unroll
            for (int k = 0; k < KNN; k++) {
                hp[k * 64 + lane]      += h0[k];
                hp[k * 64 + 32 + lane] += h1[k];
            }
        } else {
#pragma unroll
            for (int k = 0; k < KNN; k++) {
                hp[k * 64 + lane]      = h0[k];
                hp[k * 64 + 32 + lane] = h1[k];
            }
        }
        xout[(b * 64 + lane) * NN + n]      = ym0;
        xout[(b * 64 + 32 + lane) * NN + n] = ym1;
        __syncwarp();
    }
}

// ---------------- bn5 + lrelu + max over k ----------------
__global__ void bn5max_kernel(const float* __restrict__ bnp) {
    int t = blockIdx.x * blockDim.x + threadIdx.x;
    if (t >= BB * NN * 64) return;
    int o = t & 63, pn = t >> 6;
    float a = bnp[o] * rsqrtf(bnp[192 + o] + EPSBN);
    float cb = bnp[64 + o] - bnp[128 + o] * a;
    const float* hp = g_hacc + (size_t)pn * KNN * 64;
    float m = -3e38f;
#pragma unroll
    for (int k = 0; k < KNN; k++) {
        float v = a * hp[k * 64 + o] + cb;
        v = (v >= 0.f) ? v : 0.2f * v;
        m = fmaxf(m, v);
    }
    int b = pn >> 11, n = pn & (NN - 1);
    g_hm[(b * 64 + o) * NN + n] = m;
}

// ---------------- conv6 (64 -> 256) + bn6 + lrelu, transposed out ----------------
__global__ __launch_bounds__(256) void conv6_kernel(const float* __restrict__ w6,
                                                    const float* __restrict__ bnp) {
    __shared__ float sh[64 * 128]; // 32KB tile of hm
    int b = blockIdx.y, n0 = blockIdx.x * 128;
    for (int i = threadIdx.x; i < 64 * 128; i += 256) {
        int c = i >> 7, j = i & 127;
        sh[i] = g_hm[(b * 64 + c) * NN + n0 + j];
    }
    int o2 = threadIdx.x;
    float wr[64];
#pragma unroll
    for (int o = 0; o < 64; o++) wr[o] = w6[o2 * 64 + o];
    float a = bnp[o2] * rsqrtf(bnp[768 + o2] + EPSBN);
    float cb = bnp[256 + o2] - bnp[512 + o2] * a;
    __syncthreads();
    for (int jj = 0; jj < 64; jj++) {
        float s0 = 0.f, s1 = 0.f;
#pragma unroll
        for (int o = 0; o < 64; o++) {
            float2 v = *(const float2*)&sh[o * 128 + jj * 2];
            s0 += wr[o] * v.x;
            s1 += wr[o] * v.y;
        }
        float v0 = a * s0 + cb; v0 = (v0 >= 0.f) ? v0 : 0.2f * v0;
        float v1 = a * s1 + cb; v1 = (v1 >= 0.f) ? v1 : 0.2f * v1;
        g_h2t[((size_t)b * NN + n0 + jj * 2) * 256 + o2] = v0;
        g_h2t[((size_t)b * NN + n0 + jj * 2 + 1) * 256 + o2] = v1;
    }
}

// ---------------- global max + mean over N ----------------
__global__ void reduce_kernel() {
    int b = blockIdx.x, o = threadIdx.x;
    float m = -3e38f, s = 0.f;
#pragma unroll 8
    for (int n = 0; n < NN; n++) {
        float v = g_h2t[((size_t)b * NN + n) * 256 + o];
        m = fmaxf(m, v);
        s += v;
    }
    g_gvec[b * 512 + o] = m;
    g_gvec[b * 512 + 256 + o] = s * (1.0f / NN);
}

// ---------------- FC head (fc1 + fc2 + fc3 fused per-batch) ----------------
__global__ __launch_bounds__(256) void fc_kernel(
    const float* __restrict__ lw1, const float* __restrict__ lb1, const float* __restrict__ lbn1,
    const float* __restrict__ lw2, const float* __restrict__ lb2, const float* __restrict__ lbn2,
    const float* __restrict__ lw3, const float* __restrict__ lb3, float* __restrict__ out) {
    __shared__ float sg[512];
    __shared__ float sz[256];
    __shared__ float sz2[64];
    int b = blockIdx.x, t = threadIdx.x;
    sg[t] = g_gvec[b * 512 + t];
    sg[t + 256] = g_gvec[b * 512 + 256 + t];
    __syncthreads();
    {
        float acc = lb1[t];
#pragma unroll 8
        for (int i = 0; i < 512; i++) acc += lw1[t * 512 + i] * sg[i];
        float a = lbn1[t] * rsqrtf(lbn1[768 + t] + EPSBN);
        float cb = lbn1[256 + t] - lbn1[512 + t] * a;
        float v = a * acc + cb;
        sz[t] = (v >= 0.f) ? v : 0.01f * v;
    }
    __syncthreads();
    if (t < 64) {
        float acc = lb2[t];
#pragma unroll 8
        for (int i = 0; i < 256; i++) acc += lw2[t * 256 + i] * sz[i];
        float a = lbn2[t] * rsqrtf(lbn2[192 + t] + EPSBN);
        float cb = lbn2[64 + t] - lbn2[128 + t] * a;
        float v = a * acc + cb;
        sz2[t] = (v >= 0.f) ? v : 0.01f * v;
    }
    __syncthreads();
    if (t < CLSN) {
        float acc = lb3[t];
#pragma unroll
        for (int i = 0; i < 64; i++) acc += lw3[t * 64 + i] * sz2[i];
        out[b * CLSN + t] = acc;
    }
}

// ---------------- launch ----------------
extern "C" void kernel_launch(void* const* d_in, const int* in_sizes, int n_in,
                              void* d_out, int out_size) {
    const float* x    = (const float*)d_in[0];
    const float* w1   = (const float*)d_in[1];
    const float* bn1  = (const float*)d_in[2];
    const float* w2   = (const float*)d_in[3];
    const float* bn2  = (const float*)d_in[4];
    const float* w3   = (const float*)d_in[5];
    const float* bn3  = (const float*)d_in[6];
    const float* w4   = (const float*)d_in[7];
    const float* bn4  = (const float*)d_in[8];
    const float* w5   = (const float*)d_in[9];
    const float* bn5  = (const float*)d_in[10];
    const float* w6   = (const float*)d_in[11];
    const float* bn6  = (const float*)d_in[12];
    const float* lw1  = (const float*)d_in[13];
    const float* lb1  = (const float*)d_in[14];
    const float* lbn1 = (const float*)d_in[15];
    const float* lw2  = (const float*)d_in[16];
    const float* lb2  = (const float*)d_in[17];
    const float* lbn2 = (const float*)d_in[18];
    const float* lw3  = (const float*)d_in[19];
    const float* lb3  = (const float*)d_in[20];
    float* out = (float*)d_out;
    (void)in_sizes; (void)n_in; (void)out_size;

    dim3 knn_grid(NN / 128, BB);
    const int EG = 592; // edge grid

    // stage 1 (input C=3)
    xx_kernel<3><<<(BB * NN + 255) / 256, 256>>>(x, -1);
    knn3_kernel<<<knn_grid, 128>>>(x);
    edge_kernel<3><<<EG, 96>>>(x, -1, w1, bn1, w5, 0, 0, /*selout=*/0);
    // stage 2
    xx_kernel<64><<<(BB * NN + 255) / 256, 256>>>(nullptr, 0);
    knn64_kernel<<<knn_grid, 128>>>(0);
    edge_kernel<64><<<EG, 96>>>(nullptr, 0, w2, bn2, w5, 64, 1, 1);
    // stage 3
    xx_kernel<64><<<(BB * NN + 255) / 256, 256>>>(nullptr, 1);
    knn64_kernel<<<knn_grid, 128>>>(1);
    edge_kernel<64><<<EG, 96>>>(nullptr, 1, w3, bn3, w5, 128, 1, 0);
    // stage 4
    xx_kernel<64><<<(BB * NN + 255) / 256, 256>>>(nullptr, 0);
    knn64_kernel<<<knn_grid, 128>>>(0);
    edge_kernel<64><<<EG, 96>>>(nullptr, 0, w4, bn4, w5, 192, 1, 1);
    // tail
    bn5max_kernel<<<(BB * NN * 64 + 255) / 256, 256>>>(bn5);
    conv6_kernel<<<dim3(NN / 128, BB), 256>>>(w6, bn6);
    reduce_kernel<<<BB, 256>>>();
    fc_kernel<<<BB, 256>>>(lw1, lb1, lbn1, lw2, lb2, lbn2, lw3, lb3, out);
}

// round 9
// speedup vs baseline: 1.2271x; 1.2271x over previous
#include <cuda_runtime.h>
#include <math.h>

#define BB   8
#define NN   2048
#define KNN  20
#define CLSN 40
#define EPSBN 1e-5f
#define PTS  (BB * NN)

// ---------------- scratch (static __device__ — no allocations) ----------------
__device__ float g_xx[PTS];
__device__ float g_xt3[PTS * 3];                       // input transposed [n][3]
__device__ int   g_idx[PTS * KNN];
__device__ float g_feat[2][BB * 64 * NN];              // [c][n] layout (for knn)
__device__ float g_featt[2][(size_t)PTS * 64];         // [n][c] layout (for gather)
__device__ float g_base[PTS * 64];                     // (Wc-Wd)@ctr per point
__device__ float g_hacc[(size_t)PTS * KNN * 64];       // accumulated w5 @ [y1..y3]
__device__ float g_hm[BB * 64 * NN];                   // after bn5+lrelu+max_k
__device__ float g_h2t[(size_t)PTS * 256];             // conv6 out, [b][n][256]
__device__ float g_gvec[BB * 512];                     // [max | mean]

// ---------------- stage-1 norms + transpose ----------------
__global__ void xx3t_kernel(const float* __restrict__ x) {
    int t = blockIdx.x * blockDim.x + threadIdx.x;
    if (t >= PTS) return;
    int b = t / NN, n = t % NN;
    float v0 = x[(b * 3 + 0) * NN + n];
    float v1 = x[(b * 3 + 1) * NN + n];
    float v2 = x[(b * 3 + 2) * NN + n];
    g_xx[t] = v0 * v0 + v1 * v1 + v2 * v2;
    g_xt3[t * 3 + 0] = v0;
    g_xt3[t * 3 + 1] = v1;
    g_xt3[t * 3 + 2] = v2;
}

// ---------------- top-k maintenance (streaming insertion, stable) ----------------
struct TopK {
    float v[KNN];
    int   id[KNN];
    float thr;
    __device__ __forceinline__ void init() {
#pragma unroll
        for (int i = 0; i < KNN; i++) { v[i] = -3e38f; id[i] = 0; }
        thr = -3e38f;
    }
    __device__ __forceinline__ void push(float val, int m) {
        if (val > thr) {
            int p = KNN - 1;
            while (p > 0 && v[p - 1] < val) {
                v[p] = v[p - 1];
                id[p] = id[p - 1];
                p--;
            }
            v[p] = val;
            id[p] = m;
            thr = v[KNN - 1];
        }
    }
};

// ---------------- kNN, C=3 (stage 1) ----------------
__global__ __launch_bounds__(128) void knn3_kernel(const float* __restrict__ x) {
    __shared__ float s0[NN], s1[NN], s2[NN], sxx[NN]; // 32KB
    int b = blockIdx.y;
    int n = blockIdx.x * 128 + threadIdx.x;
    for (int i = threadIdx.x; i < NN; i += 128) {
        s0[i] = x[(b * 3 + 0) * NN + i];
        s1[i] = x[(b * 3 + 1) * NN + i];
        s2[i] = x[(b * 3 + 2) * NN + i];
        sxx[i] = g_xx[b * NN + i];
    }
    __syncthreads();
    float q0 = s0[n], q1 = s1[n], q2 = s2[n], xq = sxx[n];
    TopK tk; tk.init();
    for (int m = 0; m < NN; m++) {
        float d = q0 * s0[m] + q1 * s1[m] + q2 * s2[m];
        tk.push(2.f * d - xq - sxx[m], m);
    }
    int* op = g_idx + (b * NN + n) * KNN;
#pragma unroll
    for (int k = 0; k < KNN; k++) op[k] = tk.id[k];
}

// ---------------- kNN, C=64 (stages 2-4), 2-way candidate split ----------------
// 128 threads: 64 queries x 2 m-halves; stable merge of two sorted top-20 lists.
__global__ __launch_bounds__(128) void knn64_kernel(int sel) {
    const float* x = g_feat[sel];                // [b][64][NN]
    __shared__ float4 s4[2][64 * 8];             // per-group tile: [c][j4], 32 cands
    __shared__ float  sxx[2][32];
    __shared__ float  mv[64][KNN];
    __shared__ int    mi[64][KNN];
    int b = blockIdx.y;
    int q = threadIdx.x & 63;                    // query slot
    int g = threadIdx.x >> 6;                    // m-half (warp-uniform)
    int n = blockIdx.x * 64 + q;
    float qf[64];
#pragma unroll
    for (int c = 0; c < 64; c++) qf[c] = x[(b * 64 + c) * NN + n];
    float xq = g_xx[b * NN + n];
    TopK tk; tk.init();
    int mbase = g * 1024;
    for (int m0 = 0; m0 < 1024; m0 += 32) {
        __syncthreads();
        for (int i = q; i < 64 * 8; i += 64) {   // 512 float4 = 64 ch x 32 cands
            int c = i >> 3, j = i & 7;
            s4[g][i] = *(const float4*)&x[(b * 64 + c) * NN + mbase + m0 + j * 4];
        }
        if (q < 32) sxx[g][q] = g_xx[b * NN + mbase + m0 + q];
        __syncthreads();
#pragma unroll 2
        for (int j = 0; j < 8; j++) {
            float4 d = make_float4(0.f, 0.f, 0.f, 0.f);
#pragma unroll
            for (int c = 0; c < 64; c++) {
                float4 v = s4[g][c * 8 + j];
                float  qc = qf[c];
                d.x += qc * v.x; d.y += qc * v.y; d.z += qc * v.z; d.w += qc * v.w;
            }
            int m = mbase + m0 + j * 4;
            tk.push(2.f * d.x - xq - sxx[g][j * 4 + 0], m + 0);
            tk.push(2.f * d.y - xq - sxx[g][j * 4 + 1], m + 1);
            tk.push(2.f * d.z - xq - sxx[g][j * 4 + 2], m + 2);
            tk.push(2.f * d.w - xq - sxx[g][j * 4 + 3], m + 3);
        }
    }
    __syncthreads();
    if (g == 1) {
#pragma unroll
        for (int k = 0; k < KNN; k++) { mv[q][k] = tk.v[k]; mi[q][k] = tk.id[k]; }
    }
    __syncthreads();
    if (g == 0) {
        // stable merge: all group-0 indices < group-1 indices, so ties prefer A
        int ia = 0, ib = 0;
        int* op = g_idx + (b * NN + n) * KNN;
#pragma unroll
        for (int k = 0; k < KNN; k++) {
            float av = tk.v[ia], bv = mv[q][ib];
            bool ta = (av >= bv);
            op[k] = ta ? tk.id[ia] : mi[q][ib];
            if (ta) ia++; else ib++;
        }
    }
}

// ---------------- base = (Wc - Wd) @ ctr, bulk GEMM ----------------
template <int C>
__global__ __launch_bounds__(128) void base_kernel(const float* __restrict__ w, int selt) {
    __shared__ float wcd[64 * C];
    const float* xt = (C == 3) ? g_xt3 : g_featt[selt];
    int tid = threadIdx.x;
    for (int i = tid; i < 64 * C; i += 128) {
        int o = i / C, c = i - o * C;
        wcd[i] = w[o * 2 * C + C + c] - w[o * 2 * C + c];
    }
    __syncthreads();
    int p = blockIdx.x * 128 + tid;
    float xr[C];
#pragma unroll
    for (int c = 0; c < C; c++) xr[c] = xt[(size_t)p * C + c];
#pragma unroll 4
    for (int o = 0; o < 64; o++) {
        float a = 0.f;
#pragma unroll
        for (int c = 0; c < C; c++) a += wcd[o * C + c] * xr[c];
        g_base[p * 64 + o] = a;
    }
}

// ---------------- EdgeConv + fused w5-slice accumulate (+ optional bn5/max fuse) ----------------
template <int C, int ACCUM, int FINAL, int WRITEX>
__global__ __launch_bounds__(96) void edge_kernel(
    int selin,
    const float* __restrict__ w,    // [64][2C] (Wd = first C cols)
    const float* __restrict__ bnp,  // [4][64]
    const float* __restrict__ w5,   // [64][256]
    int w5off, int selout,
    const float* __restrict__ bnp5) // [4][64] (FINAL only)
{
    __shared__ float sm[C * 64 + 4096 + 3 * 1280];
    __shared__ int   sid[3][KNN];
    const float* xin_t = (C == 3) ? g_xt3 : g_featt[selin];
    float* xout  = g_feat[selout];
    float* xoutt = g_featt[selout];
    float* wd2 = sm;                 // [C][64]: (Wd[j][c], Wd[j+32][c]) interleaved
    float* w52 = sm + C * 64;        // [64][64]: (w5[j][off+o], w5[j+32][off+o])
    int tid = threadIdx.x;
    float* wbuf = sm + C * 64 + 4096 + (tid >> 5) * 1280;

    for (int i = tid; i < C * 64; i += 96) {
        int c = i >> 6, t2 = i & 63, jj = t2 >> 1, hi = t2 & 1;
        wd2[i] = w[(jj + 32 * hi) * (2 * C) + c];
    }
    for (int i = tid; i < 4096; i += 96) {
        int o = i >> 6, t2 = i & 63, jj = t2 >> 1, hi = t2 & 1;
        w52[i] = w5[(jj + 32 * hi) * 256 + w5off + o];
    }
    __syncthreads();

    int lane = tid & 31, warp = tid >> 5;
    int* myid = sid[warp];
    float a0 = bnp[lane] * rsqrtf(bnp[192 + lane] + EPSBN);
    float c0 = bnp[64 + lane] - bnp[128 + lane] * a0;
    float a1 = bnp[32 + lane] * rsqrtf(bnp[224 + lane] + EPSBN);
    float c1 = bnp[96 + lane] - bnp[160 + lane] * a1;
    float a5l = 0.f, c5l = 0.f, a5h = 0.f, c5h = 0.f;
    if (FINAL) {
        a5l = bnp5[lane] * rsqrtf(bnp5[192 + lane] + EPSBN);
        c5l = bnp5[64 + lane] - bnp5[128 + lane] * a5l;
        a5h = bnp5[32 + lane] * rsqrtf(bnp5[224 + lane] + EPSBN);
        c5h = bnp5[96 + lane] - bnp5[160 + lane] * a5h;
    }

    for (int p = blockIdx.x * 3 + warp; p < PTS; p += gridDim.x * 3) {
        int b = p >> 11, n = p & (NN - 1);
        float base0 = g_base[p * 64 + lane];
        float base1 = g_base[p * 64 + 32 + lane];
        if (lane < KNN) myid[lane] = g_idx[p * KNN + lane];
        __syncwarp();
        // gather neighbor rows (contiguous [n][c]) -> transpose into wbuf[c][k]
        if (C == 64) {
#pragma unroll
            for (int i = 0; i < 10; i++) {
                int idx = lane + i * 32;          // 0..319
                int k = idx >> 4, c4 = idx & 15;
                int nb = myid[k];
                float4 v = *(const float4*)&xin_t[((size_t)b * NN + nb) * 64 + c4 * 4];
                wbuf[(c4 * 4 + 0) * KNN + k] = v.x;
                wbuf[(c4 * 4 + 1) * KNN + k] = v.y;
                wbuf[(c4 * 4 + 2) * KNN + k] = v.z;
                wbuf[(c4 * 4 + 3) * KNN + k] = v.w;
            }
        } else {
            for (int t = lane; t < C * KNN; t += 32) {
                int k = t / C, c = t - k * C;
                wbuf[c * KNN + k] = xin_t[((size_t)b * NN + myid[k]) * C + c];
            }
        }
        __syncwarp();
        // Y = Wd @ nbr + base
        float acc0[KNN], acc1[KNN];
#pragma unroll
        for (int k = 0; k < KNN; k++) { acc0[k] = base0; acc1[k] = base1; }
#pragma unroll 4
        for (int c = 0; c < C; c++) {
            float2 wv = *(const float2*)&wd2[c * 64 + 2 * lane];
            const float4* nb4 = (const float4*)&wbuf[c * KNN];
#pragma unroll
            for (int qd = 0; qd < 5; qd++) {
                float4 v = nb4[qd];
                acc0[4 * qd + 0] += wv.x * v.x; acc0[4 * qd + 1] += wv.x * v.y;
                acc0[4 * qd + 2] += wv.x * v.z; acc0[4 * qd + 3] += wv.x * v.w;
                acc1[4 * qd + 0] += wv.y * v.x; acc1[4 * qd + 1] += wv.y * v.y;
                acc1[4 * qd + 2] += wv.y * v.z; acc1[4 * qd + 3] += wv.y * v.w;
            }
        }
        __syncwarp();
        // bn + lrelu + running max; store y into wbuf[o][k]
        float ym0 = -3e38f, ym1 = -3e38f;
#pragma unroll
        for (int k = 0; k < KNN; k++) {
            float y0 = a0 * acc0[k] + c0; y0 = (y0 >= 0.f) ? y0 : 0.2f * y0;
            float y1 = a1 * acc1[k] + c1; y1 = (y1 >= 0.f) ? y1 : 0.2f * y1;
            ym0 = fmaxf(ym0, y0);
            ym1 = fmaxf(ym1, y1);
            wbuf[lane * KNN + k] = y0;
            wbuf[(lane + 32) * KNN + k] = y1;
        }
        __syncwarp();
        // H = Y @ w5slice^T
        float h0[KNN], h1[KNN];
#pragma unroll
        for (int k = 0; k < KNN; k++) { h0[k] = 0.f; h1[k] = 0.f; }
#pragma unroll 4
        for (int o = 0; o < 64; o++) {
            float2 wv = *(const float2*)&w52[o * 64 + 2 * lane];
            const float4* y4 = (const float4*)&wbuf[o * KNN];
#pragma unroll
            for (int qd = 0; qd < 5; qd++) {
                float4 v = y4[qd];
                h0[4 * qd + 0] += wv.x * v.x; h0[4 * qd + 1] += wv.x * v.y;
                h0[4 * qd + 2] += wv.x * v.z; h0[4 * qd + 3] += wv.x * v.w;
                h1[4 * qd + 0] += wv.y * v.x; h1[4 * qd + 1] += wv.y * v.y;
                h1[4 * qd + 2] += wv.y * v.z; h1[4 * qd + 3] += wv.y * v.w;
            }
        }
        float* hp = g_hacc + (size_t)p * KNN * 64;
        if (FINAL) {
            // bn5 + lrelu + max over k, fused (hacc not re-written)
            float m0 = -3e38f, m1 = -3e38f;
#pragma unroll
            for (int k = 0; k < KNN; k++) {
                float v0 = a5l * (hp[k * 64 + lane] + h0[k]) + c5l;
                v0 = (v0 >= 0.f) ? v0 : 0.2f * v0;
                float v1 = a5h * (hp[k * 64 + 32 + lane] + h1[k]) + c5h;
                v1 = (v1 >= 0.f) ? v1 : 0.2f * v1;
                m0 = fmaxf(m0, v0);
                m1 = fmaxf(m1, v1);
            }
            g_hm[(b * 64 + lane) * NN + n]      = m0;
            g_hm[(b * 64 + 32 + lane) * NN + n] = m1;
        } else if (ACCUM) {
#pragma unroll
            for (int k = 0; k < KNN; k++) {
                hp[k * 64 + lane]      += h0[k];
                hp[k * 64 + 32 + lane] += h1[k];
            }
        } else {
#pragma unroll
            for (int k = 0; k < KNN; k++) {
                hp[k * 64 + lane]      = h0[k];
                hp[k * 64 + 32 + lane] = h1[k];
            }
        }
        if (WRITEX) {
            xout[(b * 64 + lane) * NN + n]      = ym0;
            xout[(b * 64 + 32 + lane) * NN + n] = ym1;
            xoutt[((size_t)b * NN + n) * 64 + lane]      = ym0;
            xoutt[((size_t)b * NN + n) * 64 + 32 + lane] = ym1;
            // fused squared-norm (for next stage's kNN)
            float xxv = ym0 * ym0 + ym1 * ym1;
#pragma unroll
            for (int off = 16; off > 0; off >>= 1)
                xxv += __shfl_xor_sync(0xffffffffu, xxv, off);
            if (lane == 0) g_xx[p] = xxv;
        }
        __syncwarp();
    }
}

// ---------------- conv6 (64 -> 256) + bn6 + lrelu, transposed out ----------------
__global__ __launch_bounds__(256) void conv6_kernel(const float* __restrict__ w6,
                                                    const float* __restrict__ bnp) {
    __shared__ float sh[64 * 128]; // 32KB tile of hm
    int b = blockIdx.y, n0 = blockIdx.x * 128;
    for (int i = threadIdx.x; i < 64 * 128; i += 256) {
        int c = i >> 7, j = i & 127;
        sh[i] = g_hm[(b * 64 + c) * NN + n0 + j];
    }
    int o2 = threadIdx.x;
    float wr[64];
#pragma unroll
    for (int o = 0; o < 64; o++) wr[o] = w6[o2 * 64 + o];
    float a = bnp[o2] * rsqrtf(bnp[768 + o2] + EPSBN);
    float cb = bnp[256 + o2] - bnp[512 + o2] * a;
    __syncthreads();
    for (int jj = 0; jj < 64; jj++) {
        float s0 = 0.f, s1 = 0.f;
#pragma unroll
        for (int o = 0; o < 64; o++) {
            float2 v = *(const float2*)&sh[o * 128 + jj * 2];
            s0 += wr[o] * v.x;
            s1 += wr[o] * v.y;
        }
        float v0 = a * s0 + cb; v0 = (v0 >= 0.f) ? v0 : 0.2f * v0;
        float v1 = a * s1 + cb; v1 = (v1 >= 0.f) ? v1 : 0.2f * v1;
        g_h2t[((size_t)b * NN + n0 + jj * 2) * 256 + o2] = v0;
        g_h2t[((size_t)b * NN + n0 + jj * 2 + 1) * 256 + o2] = v1;
    }
}

// ---------------- global max + mean over N ----------------
__global__ void reduce_kernel() {
    int b = blockIdx.x, o = threadIdx.x;
    float m = -3e38f, s = 0.f;
#pragma unroll 8
    for (int n = 0; n < NN; n++) {
        float v = g_h2t[((size_t)b * NN + n) * 256 + o];
        m = fmaxf(m, v);
        s += v;
    }
    g_gvec[b * 512 + o] = m;
    g_gvec[b * 512 + 256 + o] = s * (1.0f / NN);
}

// ---------------- FC head (fc1 + fc2 + fc3 fused per-batch) ----------------
__global__ __launch_bounds__(256) void fc_kernel(
    const float* __restrict__ lw1, const float* __restrict__ lb1, const float* __restrict__ lbn1,
    const float* __restrict__ lw2, const float* __restrict__ lb2, const float* __restrict__ lbn2,
    const float* __restrict__ lw3, const float* __restrict__ lb3, float* __restrict__ out) {
    __shared__ float sg[512];
    __shared__ float sz[256];
    __shared__ float sz2[64];
    int b = blockIdx.x, t = threadIdx.x;
    sg[t] = g_gvec[b * 512 + t];
    sg[t + 256] = g_gvec[b * 512 + 256 + t];
    __syncthreads();
    {
        float acc = lb1[t];
#pragma unroll 8
        for (int i = 0; i < 512; i++) acc += lw1[t * 512 + i] * sg[i];
        float a = lbn1[t] * rsqrtf(lbn1[768 + t] + EPSBN);
        float cb = lbn1[256 + t] - lbn1[512 + t] * a;
        float v = a * acc + cb;
        sz[t] = (v >= 0.f) ? v : 0.01f * v;
    }
    __syncthreads();
    if (t < 64) {
        float acc = lb2[t];
#pragma unroll 8
        for (int i = 0; i < 256; i++) acc += lw2[t * 256 + i] * sz[i];
        float a = lbn2[t] * rsqrtf(lbn2[192 + t] + EPSBN);
        float cb = lbn2[64 + t] - lbn2[128 + t] * a;
        float v = a * acc + cb;
        sz2[t] = (v >= 0.f) ? v : 0.01f * v;
    }
    __syncthreads();
    if (t < CLSN) {
        float acc = lb3[t];
#pragma unroll
        for (int i = 0; i < 64; i++) acc += lw3[t * 64 + i] * sz2[i];
        out[b * CLSN + t] = acc;
    }
}

// ---------------- launch ----------------
extern "C" void kernel_launch(void* const* d_in, const int* in_sizes, int n_in,
                              void* d_out, int out_size) {
    const float* x    = (const float*)d_in[0];
    const float* w1   = (const float*)d_in[1];
    const float* bn1  = (const float*)d_in[2];
    const float* w2   = (const float*)d_in[3];
    const float* bn2  = (const float*)d_in[4];
    const float* w3   = (const float*)d_in[5];
    const float* bn3  = (const float*)d_in[6];
    const float* w4   = (const float*)d_in[7];
    const float* bn4  = (const float*)d_in[8];
    const float* w5   = (const float*)d_in[9];
    const float* bn5  = (const float*)d_in[10];
    const float* w6   = (const float*)d_in[11];
    const float* bn6  = (const float*)d_in[12];
    const float* lw1  = (const float*)d_in[13];
    const float* lb1  = (const float*)d_in[14];
    const float* lbn1 = (const float*)d_in[15];
    const float* lw2  = (const float*)d_in[16];
    const float* lb2  = (const float*)d_in[17];
    const float* lbn2 = (const float*)d_in[18];
    const float* lw3  = (const float*)d_in[19];
    const float* lb3  = (const float*)d_in[20];
    float* out = (float*)d_out;
    (void)in_sizes; (void)n_in; (void)out_size;

    dim3 knn3_grid(NN / 128, BB);
    dim3 knn64_grid(NN / 64, BB);
    const int EG = 592;  // edge grid: 148 SM x 4 blocks

    // stage 1 (input C=3)
    xx3t_kernel<<<(PTS + 255) / 256, 256>>>(x);
    knn3_kernel<<<knn3_grid, 128>>>(x);
    base_kernel<3><<<PTS / 128, 128>>>(w1, 0);
    edge_kernel<3, 0, 0, 1><<<EG, 96>>>(0, w1, bn1, w5, 0, /*selout=*/0, nullptr);
    // stage 2
    knn64_kernel<<<knn64_grid, 128>>>(0);
    base_kernel<64><<<PTS / 128, 128>>>(w2, 0);
    edge_kernel<64, 1, 0, 1><<<EG, 96>>>(0, w2, bn2, w5, 64, 1, nullptr);
    // stage 3
    knn64_kernel<<<knn64_grid, 128>>>(1);
    base_kernel<64><<<PTS / 128, 128>>>(w3, 1);
    edge_kernel<64, 1, 0, 1><<<EG, 96>>>(1, w3, bn3, w5, 128, 0, nullptr);
    // stage 4 (fused bn5+lrelu+max_k)
    knn64_kernel<<<knn64_grid, 128>>>(0);
    base_kernel<64><<<PTS / 128, 128>>>(w4, 0);
    edge_kernel<64, 1, 1, 0><<<EG, 96>>>(0, w4, bn4, w5, 192, 1, bn5);
    // tail
    conv6_kernel<<<dim3(NN / 128, BB), 256>>>(w6, bn6);
    reduce_kernel<<<BB, 256>>>();
    fc_kernel<<<BB, 256>>>(lw1, lb1, lbn1, lw2, lb2, lbn2, lw3, lb3, out);
}

// round 10
// speedup vs baseline: 3.2092x; 2.6154x over previous
#include <cuda_runtime.h>
#include <math.h>

#define BB   8
#define NN   2048
#define KNN  20
#define CLSN 40
#define EPSBN 1e-5f
#define PTS  (BB * NN)

// ---------------- scratch (static __device__ — no allocations) ----------------
__device__ float g_xx[PTS];
__device__ float g_xt3[PTS * 3];                       // input transposed [n][3]
__device__ int   g_idx[PTS * KNN];
__device__ float g_feat[2][BB * 64 * NN];              // [c][n] layout (for knn)
__device__ float g_featt[2][(size_t)PTS * 64];         // [n][c] layout (for gather)
__device__ float g_base[PTS * 64];                     // (Wc-Wd)@ctr per point
__device__ float g_hacc[(size_t)PTS * KNN * 64];       // accumulated w5 @ [y1..y3]
__device__ float g_hm[BB * 64 * NN];                   // after bn5+lrelu+max_k
__device__ float g_h2t[(size_t)PTS * 256];             // conv6 out, [b][n][256]
__device__ float g_pmax[BB * 32 * 256];                // partial reduce
__device__ float g_psum[BB * 32 * 256];
__device__ float g_gvec[BB * 512];                     // [max | mean]

// ---------------- stage-1 norms + transpose ----------------
__global__ void xx3t_kernel(const float* __restrict__ x) {
    int t = blockIdx.x * blockDim.x + threadIdx.x;
    if (t >= PTS) return;
    int b = t / NN, n = t % NN;
    float v0 = x[(b * 3 + 0) * NN + n];
    float v1 = x[(b * 3 + 1) * NN + n];
    float v2 = x[(b * 3 + 2) * NN + n];
    g_xx[t] = v0 * v0 + v1 * v1 + v2 * v2;
    g_xt3[t * 3 + 0] = v0;
    g_xt3[t * 3 + 1] = v1;
    g_xt3[t * 3 + 2] = v2;
}

// ---------------- top-k: register-resident bubble-carry insert ----------------
// All indexing is compile-time (fully unrolled) -> arrays stay in registers.
// Same selection + stable-tie semantics as an insertion sort with strict '<'.
struct TopK {
    float v[KNN];
    int   id[KNN];
    float thr;
    __device__ __forceinline__ void init() {
#pragma unroll
        for (int i = 0; i < KNN; i++) { v[i] = -3e38f; id[i] = 0; }
        thr = -3e38f;
    }
    __device__ __forceinline__ void push(float val, int m) {
        if (val > thr) {
            float cv = val; int ci = m;
#pragma unroll
            for (int i = 0; i < KNN; i++) {
                bool sw = (cv > v[i]);
                float nv = sw ? cv : v[i];
                int   ni = sw ? ci : id[i];
                cv = sw ? v[i] : cv;
                ci = sw ? id[i] : ci;
                v[i] = nv; id[i] = ni;
            }
            thr = v[KNN - 1];
        }
    }
};

// ---------------- kNN, C=3 (stage 1) ----------------
__global__ __launch_bounds__(128) void knn3_kernel(const float* __restrict__ x) {
    __shared__ float s0[NN], s1[NN], s2[NN], sxx[NN]; // 32KB
    int b = blockIdx.y;
    int n = blockIdx.x * 128 + threadIdx.x;
    for (int i = threadIdx.x; i < NN; i += 128) {
        s0[i] = x[(b * 3 + 0) * NN + i];
        s1[i] = x[(b * 3 + 1) * NN + i];
        s2[i] = x[(b * 3 + 2) * NN + i];
        sxx[i] = g_xx[b * NN + i];
    }
    __syncthreads();
    float q0 = s0[n], q1 = s1[n], q2 = s2[n], xq = sxx[n];
    TopK tk; tk.init();
    for (int m = 0; m < NN; m++) {
        float d = q0 * s0[m] + q1 * s1[m] + q2 * s2[m];
        tk.push(2.f * d - xq - sxx[m], m);
    }
    int* op = g_idx + (b * NN + n) * KNN;
#pragma unroll
    for (int k = 0; k < KNN; k++) op[k] = tk.id[k];
}

// ---------------- kNN, C=64 (stages 2-4), 2-way candidate split ----------------
// 128 threads: 64 queries x 2 m-halves; stable smem merge of two sorted lists.
__global__ __launch_bounds__(128) void knn64_kernel(int sel) {
    const float* x = g_feat[sel];                // [b][64][NN]
    __shared__ float4 s4[2][64 * 8];             // per-group tile: [c][j4], 32 cands
    __shared__ float  sxx[2][32];
    __shared__ float  mv[2][64][KNN];
    __shared__ int    mi[2][64][KNN];
    int b = blockIdx.y;
    int q = threadIdx.x & 63;                    // query slot
    int g = threadIdx.x >> 6;                    // m-half (warp-uniform)
    int n = blockIdx.x * 64 + q;
    float qf[64];
#pragma unroll
    for (int c = 0; c < 64; c++) qf[c] = x[(b * 64 + c) * NN + n];
    float xq = g_xx[b * NN + n];
    TopK tk; tk.init();
    int mbase = g * 1024;
    for (int m0 = 0; m0 < 1024; m0 += 32) {
        __syncthreads();
        for (int i = q; i < 64 * 8; i += 64) {   // 512 float4 = 64 ch x 32 cands
            int c = i >> 3, j = i & 7;
            s4[g][i] = *(const float4*)&x[(b * 64 + c) * NN + mbase + m0 + j * 4];
        }
        if (q < 32) sxx[g][q] = g_xx[b * NN + mbase + m0 + q];
        __syncthreads();
#pragma unroll 2
        for (int j = 0; j < 8; j++) {
            float4 d = make_float4(0.f, 0.f, 0.f, 0.f);
#pragma unroll
            for (int c = 0; c < 64; c++) {
                float4 v = s4[g][c * 8 + j];
                float  qc = qf[c];
                d.x += qc * v.x; d.y += qc * v.y; d.z += qc * v.z; d.w += qc * v.w;
            }
            int m = mbase + m0 + j * 4;
            tk.push(2.f * d.x - xq - sxx[g][j * 4 + 0], m + 0);
            tk.push(2.f * d.y - xq - sxx[g][j * 4 + 1], m + 1);
            tk.push(2.f * d.z - xq - sxx[g][j * 4 + 2], m + 2);
            tk.push(2.f * d.w - xq - sxx[g][j * 4 + 3], m + 3);
        }
    }
    __syncthreads();
    // both groups publish sorted lists to smem (static indexing only)
#pragma unroll
    for (int k = 0; k < KNN; k++) { mv[g][q][k] = tk.v[k]; mi[g][q][k] = tk.id[k]; }
    __syncthreads();
    if (threadIdx.x < 64) {
        int qq = threadIdx.x;
        // stable merge: all group-0 indices < group-1 indices, so ties prefer A
        int ia = 0, ib = 0;
        int* op = g_idx + (b * NN + blockIdx.x * 64 + qq) * KNN;
#pragma unroll
        for (int k = 0; k < KNN; k++) {
            float av = mv[0][qq][ia], bv = mv[1][qq][ib];
            bool ta = (av >= bv);
            op[k] = ta ? mi[0][qq][ia] : mi[1][qq][ib];
            if (ta) ia++; else ib++;
        }
    }
}

// ---------------- base = (Wc - Wd) @ ctr, bulk GEMM ----------------
template <int C>
__global__ __launch_bounds__(128) void base_kernel(const float* __restrict__ w, int selt) {
    __shared__ float wcd[64 * C];
    const float* xt = (C == 3) ? g_xt3 : g_featt[selt];
    int tid = threadIdx.x;
    for (int i = tid; i < 64 * C; i += 128) {
        int o = i / C, c = i - o * C;
        wcd[i] = w[o * 2 * C + C + c] - w[o * 2 * C + c];
    }
    __syncthreads();
    int p = blockIdx.x * 128 + tid;
    float xr[C];
#pragma unroll
    for (int c = 0; c < C; c++) xr[c] = xt[(size_t)p * C + c];
#pragma unroll 4
    for (int o = 0; o < 64; o++) {
        float a = 0.f;
#pragma unroll
        for (int c = 0; c < C; c++) a += wcd[o * C + c] * xr[c];
        g_base[p * 64 + o] = a;
    }
}

// ---------------- EdgeConv + fused w5-slice accumulate (+ optional bn5/max fuse) ----------------
template <int C, int ACCUM, int FINAL, int WRITEX>
__global__ __launch_bounds__(96) void edge_kernel(
    int selin,
    const float* __restrict__ w,    // [64][2C] (Wd = first C cols)
    const float* __restrict__ bnp,  // [4][64]
    const float* __restrict__ w5,   // [64][256]
    int w5off, int selout,
    const float* __restrict__ bnp5) // [4][64] (FINAL only)
{
    __shared__ float sm[C * 64 + 4096 + 3 * 1280];
    __shared__ int   sid[3][KNN];
    const float* xin_t = (C == 3) ? g_xt3 : g_featt[selin];
    float* xout  = g_feat[selout];
    float* xoutt = g_featt[selout];
    float* wd2 = sm;                 // [C][64]: (Wd[j][c], Wd[j+32][c]) interleaved
    float* w52 = sm + C * 64;        // [64][64]: (w5[j][off+o], w5[j+32][off+o])
    int tid = threadIdx.x;
    float* wbuf = sm + C * 64 + 4096 + (tid >> 5) * 1280;

    for (int i = tid; i < C * 64; i += 96) {
        int c = i >> 6, t2 = i & 63, jj = t2 >> 1, hi = t2 & 1;
        wd2[i] = w[(jj + 32 * hi) * (2 * C) + c];
    }
    for (int i = tid; i < 4096; i += 96) {
        int o = i >> 6, t2 = i & 63, jj = t2 >> 1, hi = t2 & 1;
        w52[i] = w5[(jj + 32 * hi) * 256 + w5off + o];
    }
    __syncthreads();

    int lane = tid & 31, warp = tid >> 5;
    int* myid = sid[warp];
    float a0 = bnp[lane] * rsqrtf(bnp[192 + lane] + EPSBN);
    float c0 = bnp[64 + lane] - bnp[128 + lane] * a0;
    float a1 = bnp[32 + lane] * rsqrtf(bnp[224 + lane] + EPSBN);
    float c1 = bnp[96 + lane] - bnp[160 + lane] * a1;
    float a5l = 0.f, c5l = 0.f, a5h = 0.f, c5h = 0.f;
    if (FINAL) {
        a5l = bnp5[lane] * rsqrtf(bnp5[192 + lane] + EPSBN);
        c5l = bnp5[64 + lane] - bnp5[128 + lane] * a5l;
        a5h = bnp5[32 + lane] * rsqrtf(bnp5[224 + lane] + EPSBN);
        c5h = bnp5[96 + lane] - bnp5[160 + lane] * a5h;
    }

    for (int p = blockIdx.x * 3 + warp; p < PTS; p += gridDim.x * 3) {
        int b = p >> 11, n = p & (NN - 1);
        float base0 = g_base[p * 64 + lane];
        float base1 = g_base[p * 64 + 32 + lane];
        if (lane < KNN) myid[lane] = g_idx[p * KNN + lane];
        __syncwarp();
        // gather neighbor rows (contiguous [n][c]) -> transpose into wbuf[c][k]
        if (C == 64) {
#pragma unroll
            for (int i = 0; i < 10; i++) {
                int idx = lane + i * 32;          // 0..319
                int k = idx >> 4, c4 = idx & 15;
                int nb = myid[k];
                float4 v = *(const float4*)&xin_t[((size_t)b * NN + nb) * 64 + c4 * 4];
                wbuf[(c4 * 4 + 0) * KNN + k] = v.x;
                wbuf[(c4 * 4 + 1) * KNN + k] = v.y;
                wbuf[(c4 * 4 + 2) * KNN + k] = v.z;
                wbuf[(c4 * 4 + 3) * KNN + k] = v.w;
            }
        } else {
            for (int t = lane; t < C * KNN; t += 32) {
                int k = t / C, c = t - k * C;
                wbuf[c * KNN + k] = xin_t[((size_t)b * NN + myid[k]) * C + c];
            }
        }
        __syncwarp();
        // Y = Wd @ nbr + base
        float acc0[KNN], acc1[KNN];
#pragma unroll
        for (int k = 0; k < KNN; k++) { acc0[k] = base0; acc1[k] = base1; }
#pragma unroll 4
        for (int c = 0; c < C; c++) {
            float2 wv = *(const float2*)&wd2[c * 64 + 2 * lane];
            const float4* nb4 = (const float4*)&wbuf[c * KNN];
#pragma unroll
            for (int qd = 0; qd < 5; qd++) {
                float4 v = nb4[qd];
                acc0[4 * qd + 0] += wv.x * v.x; acc0[4 * qd + 1] += wv.x * v.y;
                acc0[4 * qd + 2] += wv.x * v.z; acc0[4 * qd + 3] += wv.x * v.w;
                acc1[4 * qd + 0] += wv.y * v.x; acc1[4 * qd + 1] += wv.y * v.y;
                acc1[4 * qd + 2] += wv.y * v.z; acc1[4 * qd + 3] += wv.y * v.w;
            }
        }
        __syncwarp();
        // bn + lrelu + running max; store y into wbuf[o][k]
        float ym0 = -3e38f, ym1 = -3e38f;
#pragma unroll
        for (int k = 0; k < KNN; k++) {
            float y0 = a0 * acc0[k] + c0; y0 = (y0 >= 0.f) ? y0 : 0.2f * y0;
            float y1 = a1 * acc1[k] + c1; y1 = (y1 >= 0.f) ? y1 : 0.2f * y1;
            ym0 = fmaxf(ym0, y0);
            ym1 = fmaxf(ym1, y1);
            wbuf[lane * KNN + k] = y0;
            wbuf[(lane + 32) * KNN + k] = y1;
        }
        __syncwarp();
        // H = Y @ w5slice^T
        float h0[KNN], h1[KNN];
#pragma unroll
        for (int k = 0; k < KNN; k++) { h0[k] = 0.f; h1[k] = 0.f; }
#pragma unroll 4
        for (int o = 0; o < 64; o++) {
            float2 wv = *(const float2*)&w52[o * 64 + 2 * lane];
            const float4* y4 = (const float4*)&wbuf[o * KNN];
#pragma unroll
            for (int qd = 0; qd < 5; qd++) {
                float4 v = y4[qd];
                h0[4 * qd + 0] += wv.x * v.x; h0[4 * qd + 1] += wv.x * v.y;
                h0[4 * qd + 2] += wv.x * v.z; h0[4 * qd + 3] += wv.x * v.w;
                h1[4 * qd + 0] += wv.y * v.x; h1[4 * qd + 1] += wv.y * v.y;
                h1[4 * qd + 2] += wv.y * v.z; h1[4 * qd + 3] += wv.y * v.w;
            }
        }
        float* hp = g_hacc + (size_t)p * KNN * 64;
        if (FINAL) {
            // bn5 + lrelu + max over k, fused (hacc not re-written)
            float m0 = -3e38f, m1 = -3e38f;
#pragma unroll
            for (int k = 0; k < KNN; k++) {
                float v0 = a5l * (hp[k * 64 + lane] + h0[k]) + c5l;
                v0 = (v0 >= 0.f) ? v0 : 0.2f * v0;
                float v1 = a5h * (hp[k * 64 + 32 + lane] + h1[k]) + c5h;
                v1 = (v1 >= 0.f) ? v1 : 0.2f * v1;
                m0 = fmaxf(m0, v0);
                m1 = fmaxf(m1, v1);
            }
            g_hm[(b * 64 + lane) * NN + n]      = m0;
            g_hm[(b * 64 + 32 + lane) * NN + n] = m1;
        } else if (ACCUM) {
#pragma unroll
            for (int k = 0; k < KNN; k++) {
                hp[k * 64 + lane]      += h0[k];
                hp[k * 64 + 32 + lane] += h1[k];
            }
        } else {
#pragma unroll
            for (int k = 0; k < KNN; k++) {
                hp[k * 64 + lane]      = h0[k];
                hp[k * 64 + 32 + lane] = h1[k];
            }
        }
        if (WRITEX) {
            xout[(b * 64 + lane) * NN + n]      = ym0;
            xout[(b * 64 + 32 + lane) * NN + n] = ym1;
            xoutt[((size_t)b * NN + n) * 64 + lane]      = ym0;
            xoutt[((size_t)b * NN + n) * 64 + 32 + lane] = ym1;
            // fused squared-norm (for next stage's kNN)
            float xxv = ym0 * ym0 + ym1 * ym1;
#pragma unroll
            for (int off = 16; off > 0; off >>= 1)
                xxv += __shfl_xor_sync(0xffffffffu, xxv, off);
            if (lane == 0) g_xx[p] = xxv;
        }
        __syncwarp();
    }
}

// ---------------- conv6 (64 -> 256) + bn6 + lrelu, transposed out ----------------
__global__ __launch_bounds__(256) void conv6_kernel(const float* __restrict__ w6,
                                                    const float* __restrict__ bnp) {
    __shared__ float sh[64 * 128]; // 32KB tile of hm
    int b = blockIdx.y, n0 = blockIdx.x * 128;
    for (int i = threadIdx.x; i < 64 * 128; i += 256) {
        int c = i >> 7, j = i & 127;
        sh[i] = g_hm[(b * 64 + c) * NN + n0 + j];
    }
    int o2 = threadIdx.x;
    float wr[64];
#pragma unroll
    for (int o = 0; o < 64; o++) wr[o] = w6[o2 * 64 + o];
    float a = bnp[o2] * rsqrtf(bnp[768 + o2] + EPSBN);
    float cb = bnp[256 + o2] - bnp[512 + o2] * a;
    __syncthreads();
    for (int jj = 0; jj < 64; jj++) {
        float s0 = 0.f, s1 = 0.f;
#pragma unroll
        for (int o = 0; o < 64; o++) {
            float2 v = *(const float2*)&sh[o * 128 + jj * 2];
            s0 += wr[o] * v.x;
            s1 += wr[o] * v.y;
        }
        float v0 = a * s0 + cb; v0 = (v0 >= 0.f) ? v0 : 0.2f * v0;
        float v1 = a * s1 + cb; v1 = (v1 >= 0.f) ? v1 : 0.2f * v1;
        g_h2t[((size_t)b * NN + n0 + jj * 2) * 256 + o2] = v0;
        g_h2t[((size_t)b * NN + n0 + jj * 2 + 1) * 256 + o2] = v1;
    }
}

// ---------------- global max + mean over N (2-level) ----------------
__global__ void reduce1_kernel() {
    int b = blockIdx.y, s = blockIdx.x, o = threadIdx.x;
    float m = -3e38f, sum = 0.f;
#pragma unroll 8
    for (int j = 0; j < 64; j++) {
        float v = g_h2t[((size_t)b * NN + s * 64 + j) * 256 + o];
        m = fmaxf(m, v);
        sum += v;
    }
    g_pmax[(b * 32 + s) * 256 + o] = m;
    g_psum[(b * 32 + s) * 256 + o] = sum;
}
__global__ void reduce2_kernel() {
    int b = blockIdx.x, o = threadIdx.x;
    float m = -3e38f, s = 0.f;
#pragma unroll
    for (int j = 0; j < 32; j++) {
        m = fmaxf(m, g_pmax[(b * 32 + j) * 256 + o]);
        s += g_psum[(b * 32 + j) * 256 + o];
    }
    g_gvec[b * 512 + o] = m;
    g_gvec[b * 512 + 256 + o] = s * (1.0f / NN);
}

// ---------------- FC head (fc1 + fc2 + fc3 fused per-batch) ----------------
__global__ __launch_bounds__(256) void fc_kernel(
    const float* __restrict__ lw1, const float* __restrict__ lb1, const float* __restrict__ lbn1,
    const float* __restrict__ lw2, const float* __restrict__ lb2, const float* __restrict__ lbn2,
    const float* __restrict__ lw3, const float* __restrict__ lb3, float* __restrict__ out) {
    __shared__ float sg[512];
    __shared__ float sz[256];
    __shared__ float sz2[64];
    int b = blockIdx.x, t = threadIdx.x;
    sg[t] = g_gvec[b * 512 + t];
    sg[t + 256] = g_gvec[b * 512 + 256 + t];
    __syncthreads();
    {
        float acc = lb1[t];
#pragma unroll 8
        for (int i = 0; i < 512; i++) acc += lw1[t * 512 + i] * sg[i];
        float a = lbn1[t] * rsqrtf(lbn1[768 + t] + EPSBN);
        float cb = lbn1[256 + t] - lbn1[512 + t] * a;
        float v = a * acc + cb;
        sz[t] = (v >= 0.f) ? v : 0.01f * v;
    }
    __syncthreads();
    if (t < 64) {
        float acc = lb2[t];
#pragma unroll 8
        for (int i = 0; i < 256; i++) acc += lw2[t * 256 + i] * sz[i];
        float a = lbn2[t] * rsqrtf(lbn2[192 + t] + EPSBN);
        float cb = lbn2[64 + t] - lbn2[128 + t] * a;
        float v = a * acc + cb;
        sz2[t] = (v >= 0.f) ? v : 0.01f * v;
    }
    __syncthreads();
    if (t < CLSN) {
        float acc = lb3[t];
#pragma unroll
        for (int i = 0; i < 64; i++) acc += lw3[t * 64 + i] * sz2[i];
        out[b * CLSN + t] = acc;
    }
}

// ---------------- launch ----------------
extern "C" void kernel_launch(void* const* d_in, const int* in_sizes, int n_in,
                              void* d_out, int out_size) {
    const float* x    = (const float*)d_in[0];
    const float* w1   = (const float*)d_in[1];
    const float* bn1  = (const float*)d_in[2];
    const float* w2   = (const float*)d_in[3];
    const float* bn2  = (const float*)d_in[4];
    const float* w3   = (const float*)d_in[5];
    const float* bn3  = (const float*)d_in[6];
    const float* w4   = (const float*)d_in[7];
    const float* bn4  = (const float*)d_in[8];
    const float* w5   = (const float*)d_in[9];
    const float* bn5  = (const float*)d_in[10];
    const float* w6   = (const float*)d_in[11];
    const float* bn6  = (const float*)d_in[12];
    const float* lw1  = (const float*)d_in[13];
    const float* lb1  = (const float*)d_in[14];
    const float* lbn1 = (const float*)d_in[15];
    const float* lw2  = (const float*)d_in[16];
    const float* lb2  = (const float*)d_in[17];
    const float* lbn2 = (const float*)d_in[18];
    const float* lw3  = (const float*)d_in[19];
    const float* lb3  = (const float*)d_in[20];
    float* out = (float*)d_out;
    (void)in_sizes; (void)n_in; (void)out_size;

    dim3 knn3_grid(NN / 128, BB);
    dim3 knn64_grid(NN / 64, BB);
    const int EG = 592;  // edge grid: 148 SM x 4 blocks

    // stage 1 (input C=3)
    xx3t_kernel<<<(PTS + 255) / 256, 256>>>(x);
    knn3_kernel<<<knn3_grid, 128>>>(x);
    base_kernel<3><<<PTS / 128, 128>>>(w1, 0);
    edge_kernel<3, 0, 0, 1><<<EG, 96>>>(0, w1, bn1, w5, 0, /*selout=*/0, nullptr);
    // stage 2
    knn64_kernel<<<knn64_grid, 128>>>(0);
    base_kernel<64><<<PTS / 128, 128>>>(w2, 0);
    edge_kernel<64, 1, 0, 1><<<EG, 96>>>(0, w2, bn2, w5, 64, 1, nullptr);
    // stage 3
    knn64_kernel<<<knn64_grid, 128>>>(1);
    base_kernel<64><<<PTS / 128, 128>>>(w3, 1);
    edge_kernel<64, 1, 0, 1><<<EG, 96>>>(1, w3, bn3, w5, 128, 0, nullptr);
    // stage 4 (fused bn5+lrelu+max_k)
    knn64_kernel<<<knn64_grid, 128>>>(0);
    base_kernel<64><<<PTS / 128, 128>>>(w4, 0);
    edge_kernel<64, 1, 1, 0><<<EG, 96>>>(0, w4, bn4, w5, 192, 1, bn5);
    // tail
    conv6_kernel<<<dim3(NN / 128, BB), 256>>>(w6, bn6);
    reduce1_kernel<<<dim3(32, BB), 256>>>();
    reduce2_kernel<<<BB, 256>>>();
    fc_kernel<<<BB, 256>>>(lw1, lb1, lbn1, lw2, lb2, lbn2, lw3, lb3, out);
}

// round 12
// speedup vs baseline: 3.4063x; 1.0614x over previous
#include <cuda_runtime.h>
#include <math.h>

#define BB   8
#define NN   2048
#define KNN  20
#define CLSN 40
#define EPSBN 1e-5f
#define PTS  (BB * NN)

typedef unsigned long long ull;

// ---------------- f32x2 packed-math helpers (sm_100a) ----------------
__device__ __forceinline__ ull splat2(float x) {
    unsigned u = __float_as_uint(x);
    ull r;
    asm("mov.b64 %0, {%1, %1};" : "=l"(r) : "r"(u));
    return r;
}
__device__ __forceinline__ ull pack2(float x, float y) {
    ull r;
    asm("mov.b64 %0, {%1, %2};" : "=l"(r) : "r"(__float_as_uint(x)), "r"(__float_as_uint(y)));
    return r;
}
__device__ __forceinline__ float2 unpack2(ull v) {
    unsigned lo, hi;
    asm("mov.b64 {%0, %1}, %2;" : "=r"(lo), "=r"(hi) : "l"(v));
    return make_float2(__uint_as_float(lo), __uint_as_float(hi));
}
__device__ __forceinline__ void ffma2(ull& acc, ull a, ull b) {
    asm("fma.rn.f32x2 %0, %1, %2, %0;" : "+l"(acc) : "l"(a), "l"(b));
}

// ---------------- scratch (static __device__ — no allocations) ----------------
__device__ float g_xx[PTS];
__device__ float g_xt3[PTS * 3];
__device__ int   g_idx[PTS * KNN];
__device__ float g_feat[2][BB * 64 * NN];              // [c][n] layout (for knn)
__device__ float g_featt[2][(size_t)PTS * 64];         // [n][c] layout (for gather)
__device__ float g_base[PTS * 64];
__device__ float g_hacc[(size_t)PTS * KNN * 64];
__device__ float g_hm[BB * 64 * NN];
__device__ float g_h2t[(size_t)PTS * 256];
__device__ float g_pmax[BB * 32 * 256];
__device__ float g_psum[BB * 32 * 256];
__device__ float g_gvec[BB * 512];

// ---------------- stage-1 norms + transpose ----------------
__global__ void xx3t_kernel(const float* __restrict__ x) {
    int t = blockIdx.x * blockDim.x + threadIdx.x;
    if (t >= PTS) return;
    int b = t / NN, n = t % NN;
    float v0 = x[(b * 3 + 0) * NN + n];
    float v1 = x[(b * 3 + 1) * NN + n];
    float v2 = x[(b * 3 + 2) * NN + n];
    g_xx[t] = v0 * v0 + v1 * v1 + v2 * v2;
    g_xt3[t * 3 + 0] = v0;
    g_xt3[t * 3 + 1] = v1;
    g_xt3[t * 3 + 2] = v2;
}

// ---------------- top-k: EXACT register-resident bubble-carry insert ---------
// (R10 version — passed at rel_err 4.0e-4. Static indexing only.)
struct TopK {
    float v[KNN];
    int   id[KNN];
    float thr;
    __device__ __forceinline__ void init() {
#pragma unroll
        for (int i = 0; i < KNN; i++) { v[i] = -3e38f; id[i] = 0; }
        thr = -3e38f;
    }
    __device__ __forceinline__ void push(float val, int m) {
        if (val > thr) {
            float cv = val; int ci = m;
#pragma unroll
            for (int i = 0; i < KNN; i++) {
                bool sw = (cv > v[i]);
                float nv = sw ? cv : v[i];
                int   ni = sw ? ci : id[i];
                cv = sw ? v[i] : cv;
                ci = sw ? id[i] : ci;
                v[i] = nv; id[i] = ni;
            }
            thr = v[KNN - 1];
        }
    }
};

// ---------------- kNN, C=3 (stage 1) ----------------
__global__ __launch_bounds__(128) void knn3_kernel(const float* __restrict__ x) {
    __shared__ float s0[NN], s1[NN], s2[NN], sxx[NN];
    int b = blockIdx.y;
    int n = blockIdx.x * 128 + threadIdx.x;
    for (int i = threadIdx.x; i < NN; i += 128) {
        s0[i] = x[(b * 3 + 0) * NN + i];
        s1[i] = x[(b * 3 + 1) * NN + i];
        s2[i] = x[(b * 3 + 2) * NN + i];
        sxx[i] = g_xx[b * NN + i];
    }
    __syncthreads();
    float q0 = s0[n], q1 = s1[n], q2 = s2[n], xq = sxx[n];
    TopK tk; tk.init();
    for (int m = 0; m < NN; m++) {
        float d = q0 * s0[m] + q1 * s1[m] + q2 * s2[m];
        tk.push(2.f * d - xq - sxx[m], m);
    }
    int* op = g_idx + (b * NN + n) * KNN;
#pragma unroll
    for (int k = 0; k < KNN; k++) op[k] = tk.id[k];
}

// ---------------- kNN, C=64 (stages 2-4), 2-way split + f32x2 ----------------
__global__ __launch_bounds__(128) void knn64_kernel(int sel) {
    const float* x = g_feat[sel];                // [b][64][NN]
    __shared__ float4 s4[2][64 * 8];             // [c][j4], 32 cands/tile/group
    __shared__ float  sxx[2][32];
    __shared__ float  mv[2][64][KNN];
    __shared__ int    mi[2][64][KNN];
    int b = blockIdx.y;
    int q = threadIdx.x & 63;
    int g = threadIdx.x >> 6;                    // warp-uniform
    int n = blockIdx.x * 64 + q;
    float qf[64];
#pragma unroll
    for (int c = 0; c < 64; c++) qf[c] = x[(b * 64 + c) * NN + n];
    float xq = g_xx[b * NN + n];
    TopK tk; tk.init();
    int mbase = g * 1024;
    for (int m0 = 0; m0 < 1024; m0 += 32) {
        __syncthreads();
        for (int i = q; i < 64 * 8; i += 64) {
            int c = i >> 3, j = i & 7;
            s4[g][i] = *(const float4*)&x[(b * 64 + c) * NN + mbase + m0 + j * 4];
        }
        if (q < 32) sxx[g][q] = g_xx[b * NN + mbase + m0 + q];
        __syncthreads();
        for (int j8 = 0; j8 < 4; j8++) {         // 8 candidates per iteration
            ull d01 = 0, d23 = 0, d45 = 0, d67 = 0;
#pragma unroll
            for (int c = 0; c < 64; c++) {       // FULL unroll: qf stays in regs
                ull q2 = splat2(qf[c]);
                ulonglong2 va = *(const ulonglong2*)&s4[g][c * 8 + j8 * 2];
                ulonglong2 vb = *(const ulonglong2*)&s4[g][c * 8 + j8 * 2 + 1];
                ffma2(d01, q2, va.x); ffma2(d23, q2, va.y);
                ffma2(d45, q2, vb.x); ffma2(d67, q2, vb.y);
            }
            int m = mbase + m0 + j8 * 8;
            int jb = j8 * 8;
            float2 p;
            p = unpack2(d01);
            tk.push(2.f * p.x - xq - sxx[g][jb + 0], m + 0);
            tk.push(2.f * p.y - xq - sxx[g][jb + 1], m + 1);
            p = unpack2(d23);
            tk.push(2.f * p.x - xq - sxx[g][jb + 2], m + 2);
            tk.push(2.f * p.y - xq - sxx[g][jb + 3], m + 3);
            p = unpack2(d45);
            tk.push(2.f * p.x - xq - sxx[g][jb + 4], m + 4);
            tk.push(2.f * p.y - xq - sxx[g][jb + 5], m + 5);
            p = unpack2(d67);
            tk.push(2.f * p.x - xq - sxx[g][jb + 6], m + 6);
            tk.push(2.f * p.y - xq - sxx[g][jb + 7], m + 7);
        }
    }
    __syncthreads();
    // both groups publish sorted lists to smem (static indexing only)
#pragma unroll
    for (int k = 0; k < KNN; k++) { mv[g][q][k] = tk.v[k]; mi[g][q][k] = tk.id[k]; }
    __syncthreads();
    if (threadIdx.x < 64) {
        int qq = threadIdx.x;
        // stable merge: all group-0 indices < group-1 indices, so ties prefer A
        int ia = 0, ib = 0;
        int* op = g_idx + (b * NN + blockIdx.x * 64 + qq) * KNN;
#pragma unroll
        for (int k = 0; k < KNN; k++) {
            float av = mv[0][qq][ia], bv = mv[1][qq][ib];
            bool ta = (av >= bv);
            op[k] = ta ? mi[0][qq][ia] : mi[1][qq][ib];
            if (ta) ia++; else ib++;
        }
    }
}

// ---------------- base = (Wc - Wd) @ ctr ----------------
template <int C>
__global__ __launch_bounds__(128) void base_kernel(const float* __restrict__ w, int selt) {
    __shared__ float wcd[64 * C];
    const float* xt = (C == 3) ? g_xt3 : g_featt[selt];
    int tid = threadIdx.x;
    for (int i = tid; i < 64 * C; i += 128) {
        int o = i / C, c = i - o * C;
        wcd[i] = w[o * 2 * C + C + c] - w[o * 2 * C + c];
    }
    __syncthreads();
    int p = blockIdx.x * 128 + tid;
    float xr[C];
#pragma unroll
    for (int c = 0; c < C; c++) xr[c] = xt[(size_t)p * C + c];
#pragma unroll 4
    for (int o = 0; o < 64; o++) {
        float a = 0.f;
#pragma unroll
        for (int c = 0; c < C; c++) a += wcd[o * C + c] * xr[c];
        g_base[p * 64 + o] = a;
    }
}

// ---------------- EdgeConv + fused w5-slice accumulate, f32x2 GEMMs ----------
template <int C, int ACCUM, int FINAL, int WRITEX>
__global__ __launch_bounds__(96) void edge_kernel(
    int selin,
    const float* __restrict__ w,    // [64][2C]
    const float* __restrict__ bnp,  // [4][64]
    const float* __restrict__ w5,   // [64][256]
    int w5off, int selout,
    const float* __restrict__ bnp5)
{
    __shared__ __align__(16) float sm[C * 64 + 4096 + 3 * 1280];
    __shared__ int sid[3][KNN];
    const float* xin_t = (C == 3) ? g_xt3 : g_featt[selin];
    float* xout  = g_feat[selout];
    float* xoutt = g_featt[selout];
    float* wd2 = sm;                 // [C][64]: (Wd[j][c], Wd[j+32][c])
    float* w52 = sm + C * 64;        // [64][64]: (w5[j][off+o], w5[j+32][off+o])
    int tid = threadIdx.x;
    float* wbuf = sm + C * 64 + 4096 + (tid >> 5) * 1280;

    for (int i = tid; i < C * 64; i += 96) {
        int c = i >> 6, t2 = i & 63, jj = t2 >> 1, hi = t2 & 1;
        wd2[i] = w[(jj + 32 * hi) * (2 * C) + c];
    }
    for (int i = tid; i < 4096; i += 96) {
        int o = i >> 6, t2 = i & 63, jj = t2 >> 1, hi = t2 & 1;
        w52[i] = w5[(jj + 32 * hi) * 256 + w5off + o];
    }
    __syncthreads();

    int lane = tid & 31, warp = tid >> 5;
    int* myid = sid[warp];
    float a0 = bnp[lane] * rsqrtf(bnp[192 + lane] + EPSBN);
    float c0 = bnp[64 + lane] - bnp[128 + lane] * a0;
    float a1 = bnp[32 + lane] * rsqrtf(bnp[224 + lane] + EPSBN);
    float c1 = bnp[96 + lane] - bnp[160 + lane] * a1;
    float a5l = 0.f, c5l = 0.f, a5h = 0.f, c5h = 0.f;
    if (FINAL) {
        a5l = bnp5[lane] * rsqrtf(bnp5[192 + lane] + EPSBN);
        c5l = bnp5[64 + lane] - bnp5[128 + lane] * a5l;
        a5h = bnp5[32 + lane] * rsqrtf(bnp5[224 + lane] + EPSBN);
        c5h = bnp5[96 + lane] - bnp5[160 + lane] * a5h;
    }

    for (int p = blockIdx.x * 3 + warp; p < PTS; p += gridDim.x * 3) {
        int b = p >> 11, n = p & (NN - 1);
        if (lane < KNN) myid[lane] = g_idx[p * KNN + lane];
        __syncwarp();
        // gather neighbor rows ([n][c] contiguous) -> transpose into wbuf[c][k]
        if (C == 64) {
#pragma unroll
            for (int i = 0; i < 10; i++) {
                int idx = lane + i * 32;
                int k = idx >> 4, c4 = idx & 15;
                int nb = myid[k];
                float4 v = *(const float4*)&xin_t[((size_t)b * NN + nb) * 64 + c4 * 4];
                wbuf[(c4 * 4 + 0) * KNN + k] = v.x;
                wbuf[(c4 * 4 + 1) * KNN + k] = v.y;
                wbuf[(c4 * 4 + 2) * KNN + k] = v.z;
                wbuf[(c4 * 4 + 3) * KNN + k] = v.w;
            }
        } else {
            for (int t = lane; t < C * KNN; t += 32) {
                int k = t / C, c = t - k * C;
                wbuf[c * KNN + k] = xin_t[((size_t)b * NN + myid[k]) * C + c];
            }
        }
        __syncwarp();
        // Y = Wd @ nbr + base  (packed pairs over k)
        ull acc0p[10], acc1p[10];
        {
            ull b0 = splat2(g_base[p * 64 + lane]);
            ull b1 = splat2(g_base[p * 64 + 32 + lane]);
#pragma unroll
            for (int i = 0; i < 10; i++) { acc0p[i] = b0; acc1p[i] = b1; }
        }
#pragma unroll 8
        for (int c = 0; c < C; c++) {
            float2 wv = *(const float2*)&wd2[c * 64 + 2 * lane];
            ull wx = splat2(wv.x), wy = splat2(wv.y);
            const ulonglong2* nb2 = (const ulonglong2*)&wbuf[c * KNN];
#pragma unroll
            for (int qd = 0; qd < 5; qd++) {
                ulonglong2 v = nb2[qd];
                ffma2(acc0p[2 * qd], wx, v.x); ffma2(acc0p[2 * qd + 1], wx, v.y);
                ffma2(acc1p[2 * qd], wy, v.x); ffma2(acc1p[2 * qd + 1], wy, v.y);
            }
        }
        __syncwarp();
        // bn + lrelu + running max; y back into wbuf[o][k]
        float ym0 = -3e38f, ym1 = -3e38f;
#pragma unroll
        for (int i = 0; i < 10; i++) {
            float2 u0 = unpack2(acc0p[i]);
            float2 u1 = unpack2(acc1p[i]);
            float y00 = a0 * u0.x + c0; y00 = (y00 >= 0.f) ? y00 : 0.2f * y00;
            float y01 = a0 * u0.y + c0; y01 = (y01 >= 0.f) ? y01 : 0.2f * y01;
            float y10 = a1 * u1.x + c1; y10 = (y10 >= 0.f) ? y10 : 0.2f * y10;
            float y11 = a1 * u1.y + c1; y11 = (y11 >= 0.f) ? y11 : 0.2f * y11;
            ym0 = fmaxf(ym0, fmaxf(y00, y01));
            ym1 = fmaxf(ym1, fmaxf(y10, y11));
            *(ull*)&wbuf[lane * KNN + 2 * i]        = pack2(y00, y01);
            *(ull*)&wbuf[(lane + 32) * KNN + 2 * i] = pack2(y10, y11);
        }
        __syncwarp();
        // H = Y @ w5slice^T  (packed pairs over k)
        ull h0p[10], h1p[10];
#pragma unroll
        for (int i = 0; i < 10; i++) { h0p[i] = 0ull; h1p[i] = 0ull; }
#pragma unroll 8
        for (int o = 0; o < 64; o++) {
            float2 wv = *(const float2*)&w52[o * 64 + 2 * lane];
            ull wx = splat2(wv.x), wy = splat2(wv.y);
            const ulonglong2* y2 = (const ulonglong2*)&wbuf[o * KNN];
#pragma unroll
            for (int qd = 0; qd < 5; qd++) {
                ulonglong2 v = y2[qd];
                ffma2(h0p[2 * qd], wx, v.x); ffma2(h0p[2 * qd + 1], wx, v.y);
                ffma2(h1p[2 * qd], wy, v.x); ffma2(h1p[2 * qd + 1], wy, v.y);
            }
        }
        float* hp = g_hacc + (size_t)p * KNN * 64;
        if (FINAL) {
            float m0 = -3e38f, m1 = -3e38f;
#pragma unroll
            for (int i = 0; i < 10; i++) {
                float2 h0 = unpack2(h0p[i]);
                float2 h1 = unpack2(h1p[i]);
                float v00 = a5l * (hp[(2 * i) * 64 + lane] + h0.x) + c5l;
                v00 = (v00 >= 0.f) ? v00 : 0.2f * v00;
                float v01 = a5l * (hp[(2 * i + 1) * 64 + lane] + h0.y) + c5l;
                v01 = (v01 >= 0.f) ? v01 : 0.2f * v01;
                float v10 = a5h * (hp[(2 * i) * 64 + 32 + lane] + h1.x) + c5h;
                v10 = (v10 >= 0.f) ? v10 : 0.2f * v10;
                float v11 = a5h * (hp[(2 * i + 1) * 64 + 32 + lane] + h1.y) + c5h;
                v11 = (v11 >= 0.f) ? v11 : 0.2f * v11;
                m0 = fmaxf(m0, fmaxf(v00, v01));
                m1 = fmaxf(m1, fmaxf(v10, v11));
            }
            g_hm[(b * 64 + lane) * NN + n]      = m0;
            g_hm[(b * 64 + 32 + lane) * NN + n] = m1;
        } else if (ACCUM) {
#pragma unroll
            for (int i = 0; i < 10; i++) {
                float2 h0 = unpack2(h0p[i]);
                float2 h1 = unpack2(h1p[i]);
                hp[(2 * i) * 64 + lane]          += h0.x;
                hp[(2 * i + 1) * 64 + lane]      += h0.y;
                hp[(2 * i) * 64 + 32 + lane]     += h1.x;
                hp[(2 * i + 1) * 64 + 32 + lane] += h1.y;
            }
        } else {
#pragma unroll
            for (int i = 0; i < 10; i++) {
                float2 h0 = unpack2(h0p[i]);
                float2 h1 = unpack2(h1p[i]);
                hp[(2 * i) * 64 + lane]          = h0.x;
                hp[(2 * i + 1) * 64 + lane]      = h0.y;
                hp[(2 * i) * 64 + 32 + lane]     = h1.x;
                hp[(2 * i + 1) * 64 + 32 + lane] = h1.y;
            }
        }
        if (WRITEX) {
            xout[(b * 64 + lane) * NN + n]      = ym0;
            xout[(b * 64 + 32 + lane) * NN + n] = ym1;
            xoutt[((size_t)b * NN + n) * 64 + lane]      = ym0;
            xoutt[((size_t)b * NN + n) * 64 + 32 + lane] = ym1;
            float xxv = ym0 * ym0 + ym1 * ym1;
#pragma unroll
            for (int off = 16; off > 0; off >>= 1)
                xxv += __shfl_xor_sync(0xffffffffu, xxv, off);
            if (lane == 0) g_xx[p] = xxv;
        }
        __syncwarp();
    }
}

// ---------------- conv6 (64 -> 256) + bn6 + lrelu ----------------
__global__ __launch_bounds__(256) void conv6_kernel(const float* __restrict__ w6,
                                                    const float* __restrict__ bnp) {
    __shared__ float sh[64 * 128];
    int b = blockIdx.y, n0 = blockIdx.x * 128;
    for (int i = threadIdx.x; i < 64 * 128; i += 256) {
        int c = i >> 7, j = i & 127;
        sh[i] = g_hm[(b * 64 + c) * NN + n0 + j];
    }
    int o2 = threadIdx.x;
    float wr[64];
#pragma unroll
    for (int o = 0; o < 64; o++) wr[o] = w6[o2 * 64 + o];
    float a = bnp[o2] * rsqrtf(bnp[768 + o2] + EPSBN);
    float cb = bnp[256 + o2] - bnp[512 + o2] * a;
    __syncthreads();
    for (int jj = 0; jj < 64; jj++) {
        float s0 = 0.f, s1 = 0.f;
#pragma unroll
        for (int o = 0; o < 64; o++) {
            float2 v = *(const float2*)&sh[o * 128 + jj * 2];
            s0 += wr[o] * v.x;
            s1 += wr[o] * v.y;
        }
        float v0 = a * s0 + cb; v0 = (v0 >= 0.f) ? v0 : 0.2f * v0;
        float v1 = a * s1 + cb; v1 = (v1 >= 0.f) ? v1 : 0.2f * v1;
        g_h2t[((size_t)b * NN + n0 + jj * 2) * 256 + o2] = v0;
        g_h2t[((size_t)b * NN + n0 + jj * 2 + 1) * 256 + o2] = v1;
    }
}

// ---------------- global max + mean over N (2-level) ----------------
__global__ void reduce1_kernel() {
    int b = blockIdx.y, s = blockIdx.x, o = threadIdx.x;
    float m = -3e38f, sum = 0.f;
#pragma unroll 8
    for (int j = 0; j < 64; j++) {
        float v = g_h2t[((size_t)b * NN + s * 64 + j) * 256 + o];
        m = fmaxf(m, v);
        sum += v;
    }
    g_pmax[(b * 32 + s) * 256 + o] = m;
    g_psum[(b * 32 + s) * 256 + o] = sum;
}
__global__ void reduce2_kernel() {
    int b = blockIdx.x, o = threadIdx.x;
    float m = -3e38f, s = 0.f;
#pragma unroll
    for (int j = 0; j < 32; j++) {
        m = fmaxf(m, g_pmax[(b * 32 + j) * 256 + o]);
        s += g_psum[(b * 32 + j) * 256 + o];
    }
    g_gvec[b * 512 + o] = m;
    g_gvec[b * 512 + 256 + o] = s * (1.0f / NN);
}

// ---------------- FC head ----------------
__global__ __launch_bounds__(256) void fc_kernel(
    const float* __restrict__ lw1, const float* __restrict__ lb1, const float* __restrict__ lbn1,
    const float* __restrict__ lw2, const float* __restrict__ lb2, const float* __restrict__ lbn2,
    const float* __restrict__ lw3, const float* __restrict__ lb3, float* __restrict__ out) {
    __shared__ float sg[512];
    __shared__ float sz[256];
    __shared__ float sz2[64];
    int b = blockIdx.x, t = threadIdx.x;
    sg[t] = g_gvec[b * 512 + t];
    sg[t + 256] = g_gvec[b * 512 + 256 + t];
    __syncthreads();
    {
        float acc = lb1[t];
#pragma unroll 8
        for (int i = 0; i < 512; i++) acc += lw1[t * 512 + i] * sg[i];
        float a = lbn1[t] * rsqrtf(lbn1[768 + t] + EPSBN);
        float cb = lbn1[256 + t] - lbn1[512 + t] * a;
        float v = a * acc + cb;
        sz[t] = (v >= 0.f) ? v : 0.01f * v;
    }
    __syncthreads();
    if (t < 64) {
        float acc = lb2[t];
#pragma unroll 8
        for (int i = 0; i < 256; i++) acc += lw2[t * 256 + i] * sz[i];
        float a = lbn2[t] * rsqrtf(lbn2[192 + t] + EPSBN);
        float cb = lbn2[64 + t] - lbn2[128 + t] * a;
        float v = a * acc + cb;
        sz2[t] = (v >= 0.f) ? v : 0.01f * v;
    }
    __syncthreads();
    if (t < CLSN) {
        float acc = lb3[t];
#pragma unroll
        for (int i = 0; i < 64; i++) acc += lw3[t * 64 + i] * sz2[i];
        out[b * CLSN + t] = acc;
    }
}

// ---------------- launch ----------------
extern "C" void kernel_launch(void* const* d_in, const int* in_sizes, int n_in,
                              void* d_out, int out_size) {
    const float* x    = (const float*)d_in[0];
    const float* w1   = (const float*)d_in[1];
    const float* bn1  = (const float*)d_in[2];
    const float* w2   = (const float*)d_in[3];
    const float* bn2  = (const float*)d_in[4];
    const float* w3   = (const float*)d_in[5];
    const float* bn3  = (const float*)d_in[6];
    const float* w4   = (const float*)d_in[7];
    const float* bn4  = (const float*)d_in[8];
    const float* w5   = (const float*)d_in[9];
    const float* bn5  = (const float*)d_in[10];
    const float* w6   = (const float*)d_in[11];
    const float* bn6  = (const float*)d_in[12];
    const float* lw1  = (const float*)d_in[13];
    const float* lb1  = (const float*)d_in[14];
    const float* lbn1 = (const float*)d_in[15];
    const float* lw2  = (const float*)d_in[16];
    const float* lb2  = (const float*)d_in[17];
    const float* lbn2 = (const float*)d_in[18];
    const float* lw3  = (const float*)d_in[19];
    const float* lb3  = (const float*)d_in[20];
    float* out = (float*)d_out;
    (void)in_sizes; (void)n_in; (void)out_size;

    dim3 knn3_grid(NN / 128, BB);
    dim3 knn64_grid(NN / 64, BB);
    const int EG = 592;

    // stage 1 (input C=3)
    xx3t_kernel<<<(PTS + 255) / 256, 256>>>(x);
    knn3_kernel<<<knn3_grid, 128>>>(x);
    base_kernel<3><<<PTS / 128, 128>>>(w1, 0);
    edge_kernel<3, 0, 0, 1><<<EG, 96>>>(0, w1, bn1, w5, 0, 0, nullptr);
    // stage 2
    knn64_kernel<<<knn64_grid, 128>>>(0);
    base_kernel<64><<<PTS / 128, 128>>>(w2, 0);
    edge_kernel<64, 1, 0, 1><<<EG, 96>>>(0, w2, bn2, w5, 64, 1, nullptr);
    // stage 3
    knn64_kernel<<<knn64_grid, 128>>>(1);
    base_kernel<64><<<PTS / 128, 128>>>(w3, 1);
    edge_kernel<64, 1, 0, 1><<<EG, 96>>>(1, w3, bn3, w5, 128, 0, nullptr);
    // stage 4 (fused bn5+lrelu+max_k)
    knn64_kernel<<<knn64_grid, 128>>>(0);
    base_kernel<64><<<PTS / 128, 128>>>(w4, 0);
    edge_kernel<64, 1, 1, 0><<<EG, 96>>>(0, w4, bn4, w5, 192, 1, bn5);
    // tail
    conv6_kernel<<<dim3(NN / 128, BB), 256>>>(w6, bn6);
    reduce1_kernel<<<dim3(32, BB), 256>>>();
    reduce2_kernel<<<BB, 256>>>();
    fc_kernel<<<BB, 256>>>(lw1, lb1, lbn1, lw2, lb2, lbn2, lw3, lb3, out);
}